// round 10
// baseline (speedup 1.0000x reference)
#include <cuda_runtime.h>
#include <math.h>

#define NBATCH   64
#define TSTEPS   512
#define VDIM     512
#define HDIM     256
#define ODIM     512
#define BT_TOTAL (NBATCH * TSTEPS)   // 32768

__device__ float g_xproj[(size_t)BT_TOTAL * HDIM];  // x @ W_ih^T + b_ih
__device__ float g_hcap [(size_t)BT_TOTAL * HDIM];  // min(h_t, 1)

// ---- packed f32x2 helpers ----
#define FMA2(d, a, b) \
    asm("fma.rn.f32x2 %0, %1, %2, %0;" : "+l"(d) : "l"(a), "l"(b))
#define ADD2(d, a, b) \
    asm("add.rn.f32x2 %0, %1, %2;" : "=l"(d) : "l"(a), "l"(b))
#define PACKDUP(d, s) \
    asm("mov.b64 %0, {%1, %1};" : "=l"(d) : "f"(s))
#define PACK2(d, x, y) \
    asm("mov.b64 %0, {%1, %2};" : "=l"(d) : "f"(x), "f"(y))
#define UNPACK2(x, y, s) \
    asm("mov.b64 {%0, %1}, %2;" : "=f"(x), "=f"(y) : "l"(s))

__device__ __forceinline__ unsigned smem_u32(const void* p) {
    unsigned a;
    asm("{ .reg .u64 t; cvta.to.shared.u64 t, %1; cvt.u32.u64 %0, t; }"
        : "=r"(a) : "l"(p));
    return a;
}

// ---------------------------------------------------------------------------
// NT SGEMM, f32x2 packed. BM=128, BN=128, BK=16, 256 thr, 8x8/thread.
// SMEM rows padded to 132 floats.
// ---------------------------------------------------------------------------
template<int N, int K, bool SIG>
__global__ __launch_bounds__(256) void gemm2_kernel(
    const float* __restrict__ A, const float* __restrict__ Bw,
    const float* __restrict__ bias, float* __restrict__ C)
{
    __shared__ __align__(16) float As[16][132];
    __shared__ __align__(16) float Bs[16][132];
    const int tid = threadIdx.x;
    const int tx = tid & 15;
    const int ty = tid >> 4;
    const int m0 = blockIdx.y * 128;
    const int n0 = blockIdx.x * 128;

    unsigned long long acc[4][8];
#pragma unroll
    for (int i = 0; i < 4; i++)
#pragma unroll
        for (int j = 0; j < 8; j++) acc[i][j] = 0ull;

#pragma unroll 1
    for (int kt = 0; kt < K; kt += 16) {
#pragma unroll
        for (int i = 0; i < 2; i++) {
            int idx = tid + i * 256;
            int m = idx >> 2, kq = idx & 3;
            float4 f = *(const float4*)(A + (size_t)(m0 + m) * K + kt + kq * 4);
            As[kq*4+0][m] = f.x; As[kq*4+1][m] = f.y;
            As[kq*4+2][m] = f.z; As[kq*4+3][m] = f.w;
            float4 g = *(const float4*)(Bw + (size_t)(n0 + m) * K + kt + kq * 4);
            Bs[kq*4+0][m] = g.x; Bs[kq*4+1][m] = g.y;
            Bs[kq*4+2][m] = g.z; Bs[kq*4+3][m] = g.w;
        }
        __syncthreads();
#pragma unroll
        for (int k = 0; k < 16; k++) {
            const unsigned long long* ap =
                (const unsigned long long*)&As[k][ty*8];
            float4 b0 = *(const float4*)&Bs[k][tx*8];
            float4 b1 = *(const float4*)&Bs[k][tx*8+4];
            unsigned long long av[4];
#pragma unroll
            for (int i = 0; i < 4; i++) av[i] = ap[i];
            unsigned long long bb[8];
            PACKDUP(bb[0], b0.x); PACKDUP(bb[1], b0.y);
            PACKDUP(bb[2], b0.z); PACKDUP(bb[3], b0.w);
            PACKDUP(bb[4], b1.x); PACKDUP(bb[5], b1.y);
            PACKDUP(bb[6], b1.z); PACKDUP(bb[7], b1.w);
#pragma unroll
            for (int i = 0; i < 4; i++)
#pragma unroll
                for (int j = 0; j < 8; j++)
                    FMA2(acc[i][j], av[i], bb[j]);
        }
        __syncthreads();
    }

    float4 bv0 = *(const float4*)(bias + n0 + tx*8);
    float4 bv1 = *(const float4*)(bias + n0 + tx*8 + 4);
    float bb[8] = {bv0.x,bv0.y,bv0.z,bv0.w,bv1.x,bv1.y,bv1.z,bv1.w};
#pragma unroll
    for (int i = 0; i < 4; i++) {
        float lo[8], hi[8];
#pragma unroll
        for (int j = 0; j < 8; j++) UNPACK2(lo[j], hi[j], acc[i][j]);
        int m = m0 + ty*8 + 2*i;
#pragma unroll
        for (int h = 0; h < 2; h++) {
            float* row = h ? hi : lo;
            float v[8];
#pragma unroll
            for (int j = 0; j < 8; j++) {
                float x = row[j] + bb[j];
                if (SIG) x = __fdividef(1.f, 1.f + __expf(-x));
                v[j] = x;
            }
            float4 r0; r0.x=v[0]; r0.y=v[1]; r0.z=v[2]; r0.w=v[3];
            float4 r1; r1.x=v[4]; r1.y=v[5]; r1.z=v[6]; r1.w=v[7];
            *(float4*)(C + (size_t)(m + h) * N + n0 + tx*8)     = r0;
            *(float4*)(C + (size_t)(m + h) * N + n0 + tx*8 + 4) = r1;
        }
    }
}

// ---------------------------------------------------------------------------
// Recurrence v3b: 2-CTA cluster per batch; W_hh fully register-resident.
// Fixes vs v3: trailing cluster barrier before exit (exit-while-remote-ops-
// in-flight fault), suspend-hint try_wait, no dead remote publish at s=511.
// ---------------------------------------------------------------------------
__global__ __launch_bounds__(512) __cluster_dims__(2, 1, 1)
void rnn3_kernel(
    const float* __restrict__ prev_state,
    const float* __restrict__ W_hh,
    const float* __restrict__ b_hh,
    float* __restrict__ hn_out)
{
    __shared__ __align__(16) float hbuf[2][HDIM];
    __shared__ __align__(8)  unsigned long long mbar;

    const int tid = threadIdx.x;
    unsigned rank;
    asm("mov.u32 %0, %%cluster_ctarank;" : "=r"(rank));
    const unsigned peer = rank ^ 1u;
    const int b    = blockIdx.x >> 1;
    const int rl   = tid >> 2;             // 0..127 local row
    const int kq   = tid & 3;              // k-quarter
    const int grow = (int)rank * 128 + rl; // global row

    // Register-resident W slice: W_hh[grow][kq*64 .. +64)
    unsigned long long Wr[32];
    {
        const float2* wr = (const float2*)(W_hh + (size_t)grow * HDIM + kq * 64);
#pragma unroll
        for (int i = 0; i < 32; i++) {
            float2 w = wr[i];
            PACK2(Wr[i], w.x, w.y);
        }
    }
    if (tid < HDIM) hbuf[0][tid] = prev_state[b * HDIM + tid];
    if (tid == 0) {
        unsigned mb = smem_u32(&mbar);
        asm volatile("mbarrier.init.shared.b64 [%0], 1;" :: "r"(mb) : "memory");
    }
    __syncthreads();
    // Cluster-wide: peer's mbarrier + hbuf[0] init done before any remote op.
    asm volatile("barrier.cluster.arrive.aligned;" ::: "memory");
    asm volatile("barrier.cluster.wait.aligned;"   ::: "memory");

    const float bhh = b_hh[grow];
    const float* xrow = g_xproj + (size_t)b * TSTEPS * HDIM + grow;
    float*       gout = g_hcap  + (size_t)b * TSTEPS * HDIM + grow;

    const unsigned mb_local = smem_u32(&mbar);
    unsigned mb_peer, h0_peer, h1_peer;
    asm("mapa.shared::cluster.u32 %0, %1, %2;" : "=r"(mb_peer)
        : "r"(mb_local), "r"(peer));
    {
        unsigned h0l = smem_u32(&hbuf[0][0]);
        unsigned h1l = smem_u32(&hbuf[1][0]);
        asm("mapa.shared::cluster.u32 %0, %1, %2;" : "=r"(h0_peer)
            : "r"(h0l), "r"(peer));
        asm("mapa.shared::cluster.u32 %0, %1, %2;" : "=r"(h1_peer)
            : "r"(h1l), "r"(peer));
    }

#pragma unroll 1
    for (int s = 0; s < TSTEPS; s++) {
        const int cb = s & 1;
        if (s > 0) {
            // Wait for peer's step-(s-1) publish (acquire, cluster scope)
            unsigned parity = (unsigned)((s - 1) & 1);
            asm volatile(
                "{\n\t.reg .pred P;\n"
                "WAIT%=:\n\t"
                "mbarrier.try_wait.parity.acquire.cluster.shared::cta.b64 P, [%0], %1, 0x989680;\n\t"
                "@P bra DONE%=;\n\t"
                "bra WAIT%=;\n"
                "DONE%=:\n\t}"
                :: "r"(mb_local), "r"(parity) : "memory");
        }
        float xp = 0.f;
        if (kq == 0) xp = xrow[(size_t)s * HDIM];   // early prefetch

        const float4* hv = (const float4*)(&hbuf[cb][kq * 64]);
        unsigned long long a0 = 0ull, a1 = 0ull, a2 = 0ull, a3 = 0ull;
#pragma unroll
        for (int q = 0; q < 4; q++) {
            float4 h4a = hv[4*q + 0];
            float4 h4b = hv[4*q + 1];
            float4 h4c = hv[4*q + 2];
            float4 h4d = hv[4*q + 3];
            unsigned long long p0, p1, p2, p3, p4, p5, p6, p7;
            PACK2(p0, h4a.x, h4a.y); PACK2(p1, h4a.z, h4a.w);
            PACK2(p2, h4b.x, h4b.y); PACK2(p3, h4b.z, h4b.w);
            PACK2(p4, h4c.x, h4c.y); PACK2(p5, h4c.z, h4c.w);
            PACK2(p6, h4d.x, h4d.y); PACK2(p7, h4d.z, h4d.w);
            FMA2(a0, Wr[8*q + 0], p0);
            FMA2(a1, Wr[8*q + 1], p1);
            FMA2(a2, Wr[8*q + 2], p2);
            FMA2(a3, Wr[8*q + 3], p3);
            FMA2(a0, Wr[8*q + 4], p4);
            FMA2(a1, Wr[8*q + 5], p5);
            FMA2(a2, Wr[8*q + 6], p6);
            FMA2(a3, Wr[8*q + 7], p7);
        }
        ADD2(a0, a0, a1);
        ADD2(a2, a2, a3);
        ADD2(a0, a0, a2);
        float lo, hi; UNPACK2(lo, hi, a0);
        float sum = lo + hi;
        sum += __shfl_xor_sync(0xffffffffu, sum, 1);
        sum += __shfl_xor_sync(0xffffffffu, sum, 2);

        const bool last = (s == TSTEPS - 1);
        if (kq == 0) {
            float h = fmaxf(xp + sum + bhh, 0.f);
            gout[(size_t)s * HDIM] = fminf(h, 1.f);
            if (!last) {
                hbuf[cb ^ 1][grow] = h;                 // local
                unsigned paddr = (cb ? h0_peer : h1_peer) + (unsigned)grow * 4u;
                asm volatile("st.shared::cluster.f32 [%0], %1;"
                             :: "r"(paddr), "f"(h) : "memory");
            } else {
                hn_out[b * HDIM + grow] = h;
            }
        }
        if (!last) {
            __syncthreads();
            if (tid == 0) {
                asm volatile("fence.acq_rel.cluster;" ::: "memory");
                asm volatile(
                    "mbarrier.arrive.release.cluster.shared::cluster.b64 _, [%0];"
                    :: "r"(mb_peer) : "memory");
            }
        }
    }

    // Exit safety: no CTA may leave while peer's remote stores/arrives into
    // this CTA's SMEM may still be in flight.
    asm volatile("barrier.cluster.arrive.aligned;" ::: "memory");
    asm volatile("barrier.cluster.wait.aligned;"   ::: "memory");
}

// ---------------------------------------------------------------------------
extern "C" void kernel_launch(void* const* d_in, const int* in_sizes, int n_in,
                              void* d_out, int out_size)
{
    const float* sentence   = (const float*)d_in[0];
    const float* prev_state = (const float*)d_in[1];
    const float* W_ih  = (const float*)d_in[2];
    const float* b_ih  = (const float*)d_in[3];
    const float* W_hh  = (const float*)d_in[4];
    const float* b_hh  = (const float*)d_in[5];
    const float* W_out = (const float*)d_in[6];
    const float* b_out = (const float*)d_in[7];

    float* tags = (float*)d_out;                                   // [B,T,O]
    float* hn   = tags + (size_t)NBATCH * TSTEPS * ODIM;           // [1,B,H]

    void* xp_ptr = nullptr; cudaGetSymbolAddress(&xp_ptr, g_xproj);
    void* hc_ptr = nullptr; cudaGetSymbolAddress(&hc_ptr, g_hcap);

    // K1: x_proj = sentence @ W_ih^T + b_ih
    gemm2_kernel<HDIM, VDIM, false>
        <<<dim3(HDIM/128, BT_TOTAL/128), 256>>>(sentence, W_ih, b_ih, (float*)xp_ptr);

    // K2: serial recurrence, 2-CTA cluster per batch (static __cluster_dims__)
    rnn3_kernel<<<NBATCH * 2, 512>>>(prev_state, W_hh, b_hh, hn);

    // K3: tags = sigmoid(capped @ W_out^T + b_out)
    gemm2_kernel<ODIM, HDIM, true>
        <<<dim3(ODIM/128, BT_TOTAL/128), 256>>>((const float*)hc_ptr, W_out, b_out, tags);
}

// round 11
// speedup vs baseline: 1.5088x; 1.5088x over previous
#include <cuda_runtime.h>
#include <math.h>

#define NBATCH   64
#define TSTEPS   512
#define VDIM     512
#define HDIM     256
#define ODIM     512
#define BT_TOTAL (NBATCH * TSTEPS)   // 32768

__device__ float g_xproj[(size_t)BT_TOTAL * HDIM];  // x @ W_ih^T + b_ih
__device__ float g_hcap [(size_t)BT_TOTAL * HDIM];  // min(h_t, 1)

// ---- packed f32x2 helpers ----
#define FMA2(d, a, b) \
    asm("fma.rn.f32x2 %0, %1, %2, %0;" : "+l"(d) : "l"(a), "l"(b))
#define ADD2(d, a, b) \
    asm("add.rn.f32x2 %0, %1, %2;" : "=l"(d) : "l"(a), "l"(b))
#define PACKDUP(d, s) \
    asm("mov.b64 %0, {%1, %1};" : "=l"(d) : "f"(s))
#define PACK2(d, x, y) \
    asm("mov.b64 %0, {%1, %2};" : "=l"(d) : "f"(x), "f"(y))
#define UNPACK2(x, y, s) \
    asm("mov.b64 {%0, %1}, %2;" : "=f"(x), "=f"(y) : "l"(s))

__device__ __forceinline__ unsigned smem_u32(const void* p) {
    unsigned a;
    asm("{ .reg .u64 t; cvta.to.shared.u64 t, %1; cvt.u32.u64 %0, t; }"
        : "=r"(a) : "l"(p));
    return a;
}

// ---------------------------------------------------------------------------
// NT SGEMM, f32x2 packed. BM=128, BN=128, BK=16, 256 thr, 8x8/thread.
// (unchanged from R10: K1 measured 224.8us)
// ---------------------------------------------------------------------------
template<int N, int K, bool SIG>
__global__ __launch_bounds__(256) void gemm2_kernel(
    const float* __restrict__ A, const float* __restrict__ Bw,
    const float* __restrict__ bias, float* __restrict__ C)
{
    __shared__ __align__(16) float As[16][132];
    __shared__ __align__(16) float Bs[16][132];
    const int tid = threadIdx.x;
    const int tx = tid & 15;
    const int ty = tid >> 4;
    const int m0 = blockIdx.y * 128;
    const int n0 = blockIdx.x * 128;

    unsigned long long acc[4][8];
#pragma unroll
    for (int i = 0; i < 4; i++)
#pragma unroll
        for (int j = 0; j < 8; j++) acc[i][j] = 0ull;

#pragma unroll 1
    for (int kt = 0; kt < K; kt += 16) {
#pragma unroll
        for (int i = 0; i < 2; i++) {
            int idx = tid + i * 256;
            int m = idx >> 2, kq = idx & 3;
            float4 f = *(const float4*)(A + (size_t)(m0 + m) * K + kt + kq * 4);
            As[kq*4+0][m] = f.x; As[kq*4+1][m] = f.y;
            As[kq*4+2][m] = f.z; As[kq*4+3][m] = f.w;
            float4 g = *(const float4*)(Bw + (size_t)(n0 + m) * K + kt + kq * 4);
            Bs[kq*4+0][m] = g.x; Bs[kq*4+1][m] = g.y;
            Bs[kq*4+2][m] = g.z; Bs[kq*4+3][m] = g.w;
        }
        __syncthreads();
#pragma unroll
        for (int k = 0; k < 16; k++) {
            const unsigned long long* ap =
                (const unsigned long long*)&As[k][ty*8];
            float4 b0 = *(const float4*)&Bs[k][tx*8];
            float4 b1 = *(const float4*)&Bs[k][tx*8+4];
            unsigned long long av[4];
#pragma unroll
            for (int i = 0; i < 4; i++) av[i] = ap[i];
            unsigned long long bb[8];
            PACKDUP(bb[0], b0.x); PACKDUP(bb[1], b0.y);
            PACKDUP(bb[2], b0.z); PACKDUP(bb[3], b0.w);
            PACKDUP(bb[4], b1.x); PACKDUP(bb[5], b1.y);
            PACKDUP(bb[6], b1.z); PACKDUP(bb[7], b1.w);
#pragma unroll
            for (int i = 0; i < 4; i++)
#pragma unroll
                for (int j = 0; j < 8; j++)
                    FMA2(acc[i][j], av[i], bb[j]);
        }
        __syncthreads();
    }

    float4 bv0 = *(const float4*)(bias + n0 + tx*8);
    float4 bv1 = *(const float4*)(bias + n0 + tx*8 + 4);
    float bb[8] = {bv0.x,bv0.y,bv0.z,bv0.w,bv1.x,bv1.y,bv1.z,bv1.w};
#pragma unroll
    for (int i = 0; i < 4; i++) {
        float lo[8], hi[8];
#pragma unroll
        for (int j = 0; j < 8; j++) UNPACK2(lo[j], hi[j], acc[i][j]);
        int m = m0 + ty*8 + 2*i;
#pragma unroll
        for (int h = 0; h < 2; h++) {
            float* row = h ? hi : lo;
            float v[8];
#pragma unroll
            for (int j = 0; j < 8; j++) {
                float x = row[j] + bb[j];
                if (SIG) x = __fdividef(1.f, 1.f + __expf(-x));
                v[j] = x;
            }
            float4 r0; r0.x=v[0]; r0.y=v[1]; r0.z=v[2]; r0.w=v[3];
            float4 r1; r1.x=v[4]; r1.y=v[5]; r1.z=v[6]; r1.w=v[7];
            *(float4*)(C + (size_t)(m + h) * N + n0 + tx*8)     = r0;
            *(float4*)(C + (size_t)(m + h) * N + n0 + tx*8 + 4) = r1;
        }
    }
}

// ---------------------------------------------------------------------------
// Recurrence v4: 2-CTA cluster per batch; W_hh fully register-resident.
// h exchanged with st.async (tx-count mbarrier) — no cluster fence, no L1D
// flush. Single-waiter (tid0) + syncthreads release. expect_tx pre-armed
// between wait and sync1 so arm (strictly) precedes this step's st.asyncs,
// which causally precede the peer's stores that the arm is for.
//   slot X: read @ steps s (s&1==X), filled by peer's st.asyncs @ steps s
//   with (s+1)&1==X. Arms: slot1 @ init + steps 1,3..509; slot0 @ 0,2..508.
// ---------------------------------------------------------------------------
__global__ __launch_bounds__(512) __cluster_dims__(2, 1, 1)
void rnn4_kernel(
    const float* __restrict__ prev_state,
    const float* __restrict__ W_hh,
    const float* __restrict__ b_hh,
    float* __restrict__ hn_out)
{
    __shared__ __align__(16) float hbuf[2][HDIM];
    __shared__ __align__(16) unsigned long long mbar[2];

    const int tid = threadIdx.x;
    unsigned rank;
    asm("mov.u32 %0, %%cluster_ctarank;" : "=r"(rank));
    const unsigned peer = rank ^ 1u;
    const int b    = blockIdx.x >> 1;
    const int rl   = tid >> 2;             // 0..127 local row
    const int kq   = tid & 3;              // k-quarter
    const int grow = (int)rank * 128 + rl; // global row

    // Register-resident W slice: W_hh[grow][kq*64 .. +64) as 32 f32x2 pairs
    unsigned long long Wr[32];
    {
        const float2* wr = (const float2*)(W_hh + (size_t)grow * HDIM + kq * 64);
#pragma unroll
        for (int i = 0; i < 32; i++) {
            float2 w = wr[i];
            PACK2(Wr[i], w.x, w.y);
        }
    }
    if (tid < HDIM) hbuf[0][tid] = prev_state[b * HDIM + tid];

    const unsigned mb0 = smem_u32(&mbar[0]);
    const unsigned mb1 = smem_u32(&mbar[1]);
    if (tid == 0) {
        asm volatile("mbarrier.init.shared.b64 [%0], 1;" :: "r"(mb0) : "memory");
        asm volatile("mbarrier.init.shared.b64 [%0], 1;" :: "r"(mb1) : "memory");
        // Arm slot1 for its first fill (peer's step-0 stores)
        asm volatile("mbarrier.arrive.expect_tx.shared.b64 _, [%0], %1;"
                     :: "r"(mb1), "r"(512u) : "memory");
    }
    __syncthreads();
    // All mbarriers initialized+armed, hbuf[0] filled, before any remote op.
    asm volatile("barrier.cluster.arrive.aligned;" ::: "memory");
    asm volatile("barrier.cluster.wait.aligned;"   ::: "memory");

    const float bhh = b_hh[grow];
    const float* xrow = g_xproj + (size_t)b * TSTEPS * HDIM + grow;
    float*       gout = g_hcap  + (size_t)b * TSTEPS * HDIM + grow;

    // Peer addresses (same-offset SMEM in peer CTA)
    unsigned h0_peer, h1_peer, mb0_peer, mb1_peer;
    {
        unsigned h0l = smem_u32(&hbuf[0][0]);
        unsigned h1l = smem_u32(&hbuf[1][0]);
        asm("mapa.shared::cluster.u32 %0, %1, %2;" : "=r"(h0_peer) : "r"(h0l), "r"(peer));
        asm("mapa.shared::cluster.u32 %0, %1, %2;" : "=r"(h1_peer) : "r"(h1l), "r"(peer));
        asm("mapa.shared::cluster.u32 %0, %1, %2;" : "=r"(mb0_peer) : "r"(mb0), "r"(peer));
        asm("mapa.shared::cluster.u32 %0, %1, %2;" : "=r"(mb1_peer) : "r"(mb1), "r"(peer));
    }

#pragma unroll 1
    for (int s = 0; s < TSTEPS; s++) {
        const int cb = s & 1;
        const unsigned mb_cb = cb ? mb1 : mb0;

        // Independent gmem prefetch before any waiting
        float xp = 0.f;
        if (kq == 0) xp = xrow[(size_t)s * HDIM];

        if (tid == 0) {
            if (s > 0) {
                // n-th wait on this slot: n = (s-2+cb)>>1 ; parity = n&1
                unsigned parity = (unsigned)(((s - 2 + cb) >> 1) & 1);
                asm volatile(
                    "{\n\t.reg .pred P;\n"
                    "W%=:\n\t"
                    "mbarrier.try_wait.parity.acquire.cluster.shared::cta.b64 P, [%0], %1, 0x989680;\n\t"
                    "@P bra D%=;\n\t"
                    "bra W%=;\n"
                    "D%=:\n\t}"
                    :: "r"(mb_cb), "r"(parity) : "memory");
            }
            if (s < 510) {
                // Re-arm this slot for its next fill (during step s+1).
                // Placed before sync1 => precedes our st.asyncs of this step,
                // which causally precede the peer's stores into this slot.
                asm volatile("mbarrier.arrive.expect_tx.shared.b64 _, [%0], %1;"
                             :: "r"(mb_cb), "r"(512u) : "memory");
            }
        }
        __syncthreads();   // sync1: release waiters; hbuf[cb] fully visible

        const ulonglong2* hv = (const ulonglong2*)(&hbuf[cb][kq * 64]);
        unsigned long long a0 = 0ull, a1 = 0ull, a2 = 0ull, a3 = 0ull;
#pragma unroll
        for (int q = 0; q < 4; q++) {
            ulonglong2 v0 = hv[4*q + 0];
            ulonglong2 v1 = hv[4*q + 1];
            ulonglong2 v2 = hv[4*q + 2];
            ulonglong2 v3 = hv[4*q + 3];
            FMA2(a0, Wr[8*q + 0], v0.x);
            FMA2(a1, Wr[8*q + 1], v0.y);
            FMA2(a2, Wr[8*q + 2], v1.x);
            FMA2(a3, Wr[8*q + 3], v1.y);
            FMA2(a0, Wr[8*q + 4], v2.x);
            FMA2(a1, Wr[8*q + 5], v2.y);
            FMA2(a2, Wr[8*q + 6], v3.x);
            FMA2(a3, Wr[8*q + 7], v3.y);
        }
        ADD2(a0, a0, a1);
        ADD2(a2, a2, a3);
        ADD2(a0, a0, a2);
        float lo, hi; UNPACK2(lo, hi, a0);
        float sum = lo + hi;
        sum += __shfl_xor_sync(0xffffffffu, sum, 1);
        sum += __shfl_xor_sync(0xffffffffu, sum, 2);

        const bool last = (s == TSTEPS - 1);
        float h = 0.f;
        if (kq == 0) {
            h = fmaxf(xp + sum + bhh, 0.f);
            gout[(size_t)s * HDIM] = fminf(h, 1.f);
            if (!last) {
                hbuf[cb ^ 1][grow] = h;          // local copy (read via sync1)
            } else {
                hn_out[b * HDIM + grow] = h;
            }
        }
        if (!last) {
            __syncthreads();   // sync2: all reads of hbuf[cb] done before the
                               // st.asyncs that (causally) let the peer
                               // overwrite hbuf[cb]
            if (kq == 0) {
                unsigned dst = (cb ? h0_peer : h1_peer) + (unsigned)grow * 4u;
                unsigned mbp = cb ? mb0_peer : mb1_peer;   // peer's slot nb
                asm volatile(
                    "st.async.shared::cluster.mbarrier::complete_tx::bytes.u32 [%0], %1, [%2];"
                    :: "r"(dst), "r"(__float_as_uint(h)), "r"(mbp) : "memory");
            }
        }
    }

    // Exit safety: no CTA leaves while remote ops targeting it may be in flight.
    asm volatile("barrier.cluster.arrive.aligned;" ::: "memory");
    asm volatile("barrier.cluster.wait.aligned;"   ::: "memory");
}

// ---------------------------------------------------------------------------
extern "C" void kernel_launch(void* const* d_in, const int* in_sizes, int n_in,
                              void* d_out, int out_size)
{
    const float* sentence   = (const float*)d_in[0];
    const float* prev_state = (const float*)d_in[1];
    const float* W_ih  = (const float*)d_in[2];
    const float* b_ih  = (const float*)d_in[3];
    const float* W_hh  = (const float*)d_in[4];
    const float* b_hh  = (const float*)d_in[5];
    const float* W_out = (const float*)d_in[6];
    const float* b_out = (const float*)d_in[7];

    float* tags = (float*)d_out;                                   // [B,T,O]
    float* hn   = tags + (size_t)NBATCH * TSTEPS * ODIM;           // [1,B,H]

    void* xp_ptr = nullptr; cudaGetSymbolAddress(&xp_ptr, g_xproj);
    void* hc_ptr = nullptr; cudaGetSymbolAddress(&hc_ptr, g_hcap);

    // K1: x_proj = sentence @ W_ih^T + b_ih
    gemm2_kernel<HDIM, VDIM, false>
        <<<dim3(HDIM/128, BT_TOTAL/128), 256>>>(sentence, W_ih, b_ih, (float*)xp_ptr);

    // K2: serial recurrence, 2-CTA cluster per batch (st.async exchange)
    rnn4_kernel<<<NBATCH * 2, 512>>>(prev_state, W_hh, b_hh, hn);

    // K3: tags = sigmoid(capped @ W_out^T + b_out)
    gemm2_kernel<ODIM, HDIM, true>
        <<<dim3(ODIM/128, BT_TOTAL/128), 256>>>((const float*)hc_ptr, W_out, b_out, tags);
}